// round 3
// baseline (speedup 1.0000x reference)
#include <cuda_runtime.h>
#include <cuda_bf16.h>
#include <cstdint>

// Problem shape (fixed by the dataset):
//   N=50000 nodes, GF=256, H=20, E=800000 edges, K=400, OUT=128
#define GF      256
#define HDIM    20
#define K400    400
#define OUTD    128
#define EPT     128     // edges per CTA tile
#define TPB     256     // threads per block (edge kernel)
#define LN_EPS  1e-5f

#define MAX_N   50000

// Scratch for node projections h[N][20] (allocation-free rule: __device__ global)
__device__ float g_h[MAX_N * HDIM];

// ---------------------------------------------------------------------------
// Kernel A: h = relu(LayerNorm(node_feat @ W_node + b_node))   [N, 20]
// One warp per node. Lane l accumulates over k = l, l+32, ... for all 20 outs.
// ---------------------------------------------------------------------------
__global__ __launch_bounds__(256) void node_proj_kernel(
    const float* __restrict__ x,      // [N, 256]
    const float* __restrict__ Wn,     // [256, 20]
    const float* __restrict__ bn,     // [20]
    const float* __restrict__ gn,     // [20]
    const float* __restrict__ btn,    // [20]
    int N)
{
    __shared__ float Ws[GF * HDIM];
    __shared__ float bs[HDIM], gs[HDIM], bts[HDIM];

    int tid = threadIdx.x;
    for (int i = tid; i < GF * HDIM; i += blockDim.x) Ws[i] = Wn[i];
    if (tid < HDIM) { bs[tid] = bn[tid]; gs[tid] = gn[tid]; bts[tid] = btn[tid]; }
    __syncthreads();

    int warp = tid >> 5, lane = tid & 31;
    int n = blockIdx.x * (blockDim.x >> 5) + warp;
    if (n >= N) return;

    float acc[HDIM];
#pragma unroll
    for (int o = 0; o < HDIM; o++) acc[o] = 0.f;

    const float* xr = x + (size_t)n * GF;
#pragma unroll 2
    for (int k = lane; k < GF; k += 32) {
        float xv = xr[k];
#pragma unroll
        for (int o = 0; o < HDIM; o++)
            acc[o] = fmaf(xv, Ws[k * HDIM + o], acc[o]);
    }
#pragma unroll
    for (int o = 0; o < HDIM; o++) {
#pragma unroll
        for (int s = 16; s > 0; s >>= 1)
            acc[o] += __shfl_xor_sync(0xffffffffu, acc[o], s);
    }
    if (lane == 0) {
        float s = 0.f, s2 = 0.f;
#pragma unroll
        for (int o = 0; o < HDIM; o++) {
            float v = acc[o] + bs[o];
            acc[o] = v;
            s += v;
            s2 = fmaf(v, v, s2);
        }
        float mu  = s  * (1.0f / HDIM);
        float var = fmaf(-mu, mu, s2 * (1.0f / HDIM));
        float r   = rsqrtf(var + LN_EPS);
#pragma unroll
        for (int o = 0; o < HDIM; o++) {
            float v = fmaf((acc[o] - mu) * r, gs[o], bts[o]);
            g_h[(size_t)n * HDIM + o] = v > 0.f ? v : 0.f;
        }
    }
}

// ---------------------------------------------------------------------------
// Kernel B: per-edge   e = relu(LN(kron @ W_kron + b_kron)); scatter-sum to dst
//   kron[e, a*20+k] = h[src[e]][a] * h[dst[e]][k]  (generated on the fly)
// Persistent CTAs, W_kron resident in smem (200 KB), 128-edge tiles,
// 8 edges x 8 outputs register tile per thread, packed fma.rn.f32x2 math.
// ---------------------------------------------------------------------------
__device__ __forceinline__ void red_add_v4(float* p, float a, float b, float c, float d) {
    asm volatile("red.global.add.v4.f32 [%0], {%1,%2,%3,%4};"
                 :: "l"(p), "f"(a), "f"(b), "f"(c), "f"(d) : "memory");
}

extern __shared__ float smem[];

__global__ __launch_bounds__(TPB, 1) void edge_kernel(
    const float* __restrict__ Wk,     // [400, 128]
    const float* __restrict__ bk,     // [128]
    const float* __restrict__ gk,     // [128]
    const float* __restrict__ btk,    // [128]
    const int* __restrict__ src,      // int32! (jnp int64 downcasts w/o x64)
    const int* __restrict__ dst,
    float* __restrict__ out,          // [N, 128]
    int E)
{
    float* Ws = smem;                         // 400*128 = 51200 floats
    float* hs = Ws + K400 * OUTD;             // 20*128  =  2560 floats
    float* hd = hs + HDIM * EPT;              // 20*128
    int*   ds = (int*)(hd + HDIM * EPT);      // 128 ints

    int tid = threadIdx.x;
    int tx  = tid & 15;    // output group: outputs [tx*8, tx*8+8)
    int ty  = tid >> 4;    // edge group:   edges   [ty*8, ty*8+8) within tile
    int e0  = ty * 8;

    // Load W_kron to smem once (persistent CTA)
    {
        const float4* Wv  = (const float4*)Wk;
        float4*       Wsv = (float4*)Ws;
        for (int i = tid; i < K400 * OUTD / 4; i += TPB) Wsv[i] = Wv[i];
    }
    // Per-thread epilogue params for this thread's 8 outputs
    float bo[8], go[8], bto[8];
#pragma unroll
    for (int j = 0; j < 8; j++) {
        int o = tx * 8 + j;
        bo[j] = bk[o]; go[j] = gk[o]; bto[j] = btk[o];
    }

    int ntiles = (E + EPT - 1) / EPT;
    for (int tile = blockIdx.x; tile < ntiles; tile += gridDim.x) {
        int ebase = tile * EPT;
        __syncthreads();   // previous tile fully consumed before overwriting smem

        // ---- stage edge metadata + gather h rows (transposed: hX[a*128 + e]) ----
        if (tid < EPT) {
            int e = ebase + tid;
            ds[tid] = (e < E) ? dst[e] : -1;
        }
        {
            int e_local = tid >> 1;
            int side    = tid & 1;
            int e       = ebase + e_local;
            int idx = 0;
            if (e < E) idx = side ? dst[e] : src[e];
            const float4* hr = (const float4*)(g_h + (size_t)idx * HDIM);
            float* dsm = side ? hd : hs;
#pragma unroll
            for (int q = 0; q < 5; q++) {
                float4 v = (e < E) ? hr[q] : make_float4(0.f, 0.f, 0.f, 0.f);
                dsm[(q * 4 + 0) * EPT + e_local] = v.x;
                dsm[(q * 4 + 1) * EPT + e_local] = v.y;
                dsm[(q * 4 + 2) * EPT + e_local] = v.z;
                dsm[(q * 4 + 3) * EPT + e_local] = v.w;
            }
        }
        __syncthreads();

        // ---- main GEMM: acc[e][o] += (hs[e][a]*hd[e][k2]) * W[a*20+k2][o] ----
        unsigned long long acc[8][4];   // 8 edges x 4 packed f32x2 (8 outputs)
#pragma unroll
        for (int e = 0; e < 8; e++)
#pragma unroll
            for (int p = 0; p < 4; p++) acc[e][p] = 0ull;

#pragma unroll 1
        for (int a = 0; a < HDIM; a++) {
            float4 hsv0 = *(const float4*)&hs[a * EPT + e0];
            float4 hsv1 = *(const float4*)&hs[a * EPT + e0 + 4];
            float hsv[8] = {hsv0.x, hsv0.y, hsv0.z, hsv0.w,
                            hsv1.x, hsv1.y, hsv1.z, hsv1.w};
            const float* wbase = Ws + (a * HDIM) * OUTD + tx * 8;
#pragma unroll 5
            for (int k2 = 0; k2 < HDIM; k2++) {
                float4 hdv0 = *(const float4*)&hd[k2 * EPT + e0];
                float4 hdv1 = *(const float4*)&hd[k2 * EPT + e0 + 4];
                float hdv[8] = {hdv0.x, hdv0.y, hdv0.z, hdv0.w,
                                hdv1.x, hdv1.y, hdv1.z, hdv1.w};
                const ulonglong2* wrow = (const ulonglong2*)(wbase + k2 * OUTD);
                ulonglong2 w01 = wrow[0];
                ulonglong2 w23 = wrow[1];
                unsigned long long w[4] = {w01.x, w01.y, w23.x, w23.y};
#pragma unroll
                for (int e = 0; e < 8; e++) {
                    float t = hsv[e] * hdv[e];
                    unsigned long long t2;
                    asm("mov.b64 %0, {%1, %1};" : "=l"(t2) : "f"(t));
#pragma unroll
                    for (int p = 0; p < 4; p++)
                        asm("fma.rn.f32x2 %0, %1, %2, %0;"
                            : "+l"(acc[e][p]) : "l"(t2), "l"(w[p]));
                }
            }
        }

        // ---- epilogue: +bias, LN over 128 outputs, ReLU, scatter-add ----
#pragma unroll
        for (int ee = 0; ee < 8; ee++) {
            float vals[8];
            float s = 0.f, s2 = 0.f;
#pragma unroll
            for (int p = 0; p < 4; p++) {
                float lo, hi;
                asm("mov.b64 {%0, %1}, %2;" : "=f"(lo), "=f"(hi) : "l"(acc[ee][p]));
                lo += bo[2 * p];
                hi += bo[2 * p + 1];
                vals[2 * p]     = lo;
                vals[2 * p + 1] = hi;
                s += lo + hi;
                s2 = fmaf(lo, lo, s2);
                s2 = fmaf(hi, hi, s2);
            }
            // reduce across the 16 threads (same ty = same 8 edges, half-warp)
#pragma unroll
            for (int off = 8; off > 0; off >>= 1) {
                s  += __shfl_xor_sync(0xffffffffu, s,  off);
                s2 += __shfl_xor_sync(0xffffffffu, s2, off);
            }
            float m   = s * (1.0f / OUTD);
            float var = fmaf(-m, m, s2 * (1.0f / OUTD));
            float r   = rsqrtf(var + LN_EPS);
            int d = ds[e0 + ee];
            if (d >= 0) {
                float ov[8];
#pragma unroll
                for (int j = 0; j < 8; j++) {
                    float v = fmaf((vals[j] - m) * r, go[j], bto[j]);
                    ov[j] = v > 0.f ? v : 0.f;
                }
                float* p = out + (size_t)d * OUTD + tx * 8;
                red_add_v4(p,     ov[0], ov[1], ov[2], ov[3]);
                red_add_v4(p + 4, ov[4], ov[5], ov[6], ov[7]);
            }
        }
    }
}

// ---------------------------------------------------------------------------
// Launch. Inputs resolved by element count so metadata ordering quirks can't
// silently mis-cast anything:
//   12.8M -> node_feat | 5120 -> W_node | 51200 -> W_kron
//   20-sized in order  -> b_node, g_node, beta_node
//   128-sized in order -> b_kron, g_kron, beta_kron
//   800000-sized in order -> src, dst
// ---------------------------------------------------------------------------
extern "C" void kernel_launch(void* const* d_in, const int* in_sizes, int n_in,
                              void* d_out, int out_size)
{
    const float* node_feat = 0;
    const float* W_node = 0;
    const float* W_kron = 0;
    const float* p20[3]  = {0, 0, 0};   // b_node, g_node, beta_node
    const float* p128[3] = {0, 0, 0};   // b_kron, g_kron, beta_kron
    const int*   pE[2]   = {0, 0};      // src, dst
    int n20 = 0, n128 = 0, nE = 0;
    int E = 0, N = 0;

    for (int i = 0; i < n_in; i++) {
        int sz = in_sizes[i];
        if (sz == GF * HDIM) {
            W_node = (const float*)d_in[i];
        } else if (sz == K400 * OUTD) {
            W_kron = (const float*)d_in[i];
        } else if (sz == HDIM) {
            if (n20 < 3) p20[n20++] = (const float*)d_in[i];
        } else if (sz == OUTD) {
            if (n128 < 3) p128[n128++] = (const float*)d_in[i];
        } else if (sz > 1000000) {
            node_feat = (const float*)d_in[i];
            N = sz / GF;
        } else {
            if (nE < 2) { pE[nE++] = (const int*)d_in[i]; E = sz; }
        }
    }

    float* out = (float*)d_out;

    // out is poisoned; we accumulate with atomics -> zero it first
    cudaMemsetAsync(out, 0, (size_t)out_size * sizeof(float));

    // Kernel A: node projections (8 warps/block -> 8 nodes/block)
    node_proj_kernel<<<(N + 7) / 8, 256>>>(node_feat, W_node, p20[0],
                                           p20[1], p20[2], N);

    // Kernel B: edges (persistent grid, full-W smem residency)
    const int SMEM_BYTES = (K400 * OUTD + 2 * HDIM * EPT) * 4 + EPT * 4;
    cudaFuncSetAttribute(edge_kernel,
                         cudaFuncAttributeMaxDynamicSharedMemorySize, SMEM_BYTES);
    edge_kernel<<<148, TPB, SMEM_BYTES>>>(W_kron, p128[0], p128[1], p128[2],
                                          pE[0], pE[1], out, E);
}

// round 6
// speedup vs baseline: 2.0410x; 2.0410x over previous
#include <cuda_runtime.h>
#include <cstdint>

// Shape: N=50000, GF=256, H=20, E=800000, K=400, OUT=128
#define GF      256
#define HDIM    20
#define K400    400
#define OUTD    128
#define LN_EPS  1e-5f
#define MAX_N   50000
#define MAX_E   800000
#define MCOLS   (HDIM * OUTD)   // 2560
#define CHUNK   6400            // nodes per M tile (65.5 MB, fits L2)

// ---- device scratch (allocation-free rule) ----
__device__ float g_h[MAX_N * HDIM];                    // node projections
__device__ float g_M[(size_t)CHUNK * MCOLS];           // per-chunk M tile (65.5 MB)
__device__ int   g_cnt[MAX_N];
__device__ int   g_start[MAX_N + 1];
__device__ int   g_cursor[MAX_N];
__device__ int   g_order[MAX_E];

// ---------------------------------------------------------------------------
// Kernel A: h = relu(LayerNorm(node_feat @ W_node + b_node))   [N, 20]
// ---------------------------------------------------------------------------
__global__ __launch_bounds__(256) void node_proj_kernel(
    const float* __restrict__ x, const float* __restrict__ Wn,
    const float* __restrict__ bn, const float* __restrict__ gn,
    const float* __restrict__ btn, int N)
{
    __shared__ float Ws[GF * HDIM];
    __shared__ float bs[HDIM], gs[HDIM], bts[HDIM];

    int tid = threadIdx.x;
    for (int i = tid; i < GF * HDIM; i += blockDim.x) Ws[i] = Wn[i];
    if (tid < HDIM) { bs[tid] = bn[tid]; gs[tid] = gn[tid]; bts[tid] = btn[tid]; }
    __syncthreads();

    int warp = tid >> 5, lane = tid & 31;
    int n = blockIdx.x * (blockDim.x >> 5) + warp;
    if (n >= N) return;

    float acc[HDIM];
#pragma unroll
    for (int o = 0; o < HDIM; o++) acc[o] = 0.f;

    const float* xr = x + (size_t)n * GF;
#pragma unroll 2
    for (int k = lane; k < GF; k += 32) {
        float xv = xr[k];
#pragma unroll
        for (int o = 0; o < HDIM; o++)
            acc[o] = fmaf(xv, Ws[k * HDIM + o], acc[o]);
    }
#pragma unroll
    for (int o = 0; o < HDIM; o++) {
#pragma unroll
        for (int s = 16; s > 0; s >>= 1)
            acc[o] += __shfl_xor_sync(0xffffffffu, acc[o], s);
    }
    if (lane == 0) {
        float s = 0.f, s2 = 0.f;
#pragma unroll
        for (int o = 0; o < HDIM; o++) {
            float v = acc[o] + bs[o];
            acc[o] = v; s += v; s2 = fmaf(v, v, s2);
        }
        float mu  = s * (1.0f / HDIM);
        float var = fmaf(-mu, mu, s2 * (1.0f / HDIM));
        float r   = rsqrtf(var + LN_EPS);
#pragma unroll
        for (int o = 0; o < HDIM; o++) {
            float v = fmaf((acc[o] - mu) * r, gs[o], bts[o]);
            g_h[(size_t)n * HDIM + o] = v > 0.f ? v : 0.f;
        }
    }
}

// ---------------------------------------------------------------------------
// Sort-by-src machinery: zero -> histogram -> scan -> scatter
// ---------------------------------------------------------------------------
__global__ void zero_cnt_kernel(int N) {
    int i = blockIdx.x * blockDim.x + threadIdx.x;
    if (i < N) g_cnt[i] = 0;
}

__global__ void hist_kernel(const int* __restrict__ src, int E) {
    for (int e = blockIdx.x * blockDim.x + threadIdx.x; e < E;
         e += gridDim.x * blockDim.x)
        atomicAdd(&g_cnt[src[e]], 1);
}

__global__ __launch_bounds__(1024) void scan_kernel(int N) {
    __shared__ int warp_sums[32];
    int tid = threadIdx.x;
    int chunk = (N + 1023) >> 10;
    int base = tid * chunk;

    int s = 0;
    for (int j = 0; j < chunk; j++) {
        int i = base + j;
        if (i < N) s += g_cnt[i];
    }
    int lane = tid & 31, wid = tid >> 5;
    int v = s;
#pragma unroll
    for (int off = 1; off < 32; off <<= 1) {
        int t = __shfl_up_sync(0xffffffffu, v, off);
        if (lane >= off) v += t;
    }
    if (lane == 31) warp_sums[wid] = v;
    __syncthreads();
    if (wid == 0) {
        int w = warp_sums[lane];
#pragma unroll
        for (int off = 1; off < 32; off <<= 1) {
            int t = __shfl_up_sync(0xffffffffu, w, off);
            if (lane >= off) w += t;
        }
        warp_sums[lane] = w;   // inclusive warp totals
    }
    __syncthreads();
    int excl = v - s + (wid ? warp_sums[wid - 1] : 0);
    int run = excl;
    for (int j = 0; j < chunk; j++) {
        int i = base + j;
        if (i < N) {
            g_start[i]  = run;
            g_cursor[i] = run;
            run += g_cnt[i];
        }
    }
    if (tid == 1023) g_start[N] = run;
}

__global__ void scatter_kernel(const int* __restrict__ src, int E) {
    for (int e = blockIdx.x * blockDim.x + threadIdx.x; e < E;
         e += gridDim.x * blockDim.x) {
        int p = atomicAdd(&g_cursor[src[e]], 1);
        g_order[p] = e;
    }
}

// ---------------------------------------------------------------------------
// Kernel B (chunked): for n in [n0,n1):
//   M[n-n0][k*128+o] = sum_a h[n][a] * W[a*20+k][o]
// 64 nodes/CTA so W quads are register-cached across the node tile.
// ---------------------------------------------------------------------------
#define MB_NODES 64

__global__ __launch_bounds__(256) void m_build_kernel(
    const float* __restrict__ Wk, int n0, int n1)
{
    __shared__ float h_t[HDIM][MB_NODES];   // transposed h tile
    int tid = threadIdx.x;
    int nb = n0 + blockIdx.x * MB_NODES;

    for (int idx = tid; idx < MB_NODES * HDIM; idx += 256) {
        int i = idx / HDIM, a = idx % HDIM;
        float v = 0.f;
        if (nb + i < n1) v = g_h[(size_t)(nb + i) * HDIM + a];
        h_t[a][i] = v;
    }
    __syncthreads();

    for (int q = tid; q < MCOLS / 4; q += 256) {     // 640 quads
        int c = q * 4;
        int k = c >> 7;          // c / 128
        int o = c & 127;
        ulonglong2 Wq[HDIM];
#pragma unroll
        for (int a = 0; a < HDIM; a++)
            Wq[a] = *(const ulonglong2*)&Wk[(a * HDIM + k) * OUTD + o];

        for (int i4 = 0; i4 < MB_NODES; i4 += 4) {
            ulonglong2 acc[4];
#pragma unroll
            for (int ni = 0; ni < 4; ni++) { acc[ni].x = 0ull; acc[ni].y = 0ull; }
#pragma unroll
            for (int a = 0; a < HDIM; a++) {
                float4 h4 = *(const float4*)&h_t[a][i4];
                unsigned long long hx, hy, hz, hw;
                asm("mov.b64 %0,{%1,%1};" : "=l"(hx) : "f"(h4.x));
                asm("mov.b64 %0,{%1,%1};" : "=l"(hy) : "f"(h4.y));
                asm("mov.b64 %0,{%1,%1};" : "=l"(hz) : "f"(h4.z));
                asm("mov.b64 %0,{%1,%1};" : "=l"(hw) : "f"(h4.w));
                asm("fma.rn.f32x2 %0, %1, %2, %0;" : "+l"(acc[0].x) : "l"(hx), "l"(Wq[a].x));
                asm("fma.rn.f32x2 %0, %1, %2, %0;" : "+l"(acc[0].y) : "l"(hx), "l"(Wq[a].y));
                asm("fma.rn.f32x2 %0, %1, %2, %0;" : "+l"(acc[1].x) : "l"(hy), "l"(Wq[a].x));
                asm("fma.rn.f32x2 %0, %1, %2, %0;" : "+l"(acc[1].y) : "l"(hy), "l"(Wq[a].y));
                asm("fma.rn.f32x2 %0, %1, %2, %0;" : "+l"(acc[2].x) : "l"(hz), "l"(Wq[a].x));
                asm("fma.rn.f32x2 %0, %1, %2, %0;" : "+l"(acc[2].y) : "l"(hz), "l"(Wq[a].y));
                asm("fma.rn.f32x2 %0, %1, %2, %0;" : "+l"(acc[3].x) : "l"(hw), "l"(Wq[a].x));
                asm("fma.rn.f32x2 %0, %1, %2, %0;" : "+l"(acc[3].y) : "l"(hw), "l"(Wq[a].y));
            }
#pragma unroll
            for (int ni = 0; ni < 4; ni++) {
                int n = nb + i4 + ni;
                if (n < n1)
                    *(ulonglong2*)&g_M[(size_t)(n - n0) * MCOLS + c] = acc[ni];
            }
        }
    }
}

// ---------------------------------------------------------------------------
// Kernel D (chunked): grouped edges for src nodes in [n0,n1). Warp owns node
// n: caches M_{n} in regs (lane: cols lane*4..+3, all k), streams its edges:
//   y = h_dst @ M_n + b  -> LN -> ReLU -> red.global.add to out[dst]
// ---------------------------------------------------------------------------
__device__ __forceinline__ void red_add_v4(float* p, float a, float b, float c, float d) {
    asm volatile("red.global.add.v4.f32 [%0], {%1,%2,%3,%4};"
                 :: "l"(p), "f"(a), "f"(b), "f"(c), "f"(d) : "memory");
}

__global__ __launch_bounds__(128) void edge_group_kernel(
    const float* __restrict__ bk, const float* __restrict__ gk,
    const float* __restrict__ btk, const int* __restrict__ dst,
    float* __restrict__ out, int n0, int n1)
{
    int lane = threadIdx.x & 31;
    int gw   = (blockIdx.x * blockDim.x + threadIdx.x) >> 5;
    int NW   = (gridDim.x * blockDim.x) >> 5;

    float4 b4  = *(const float4*)&bk[lane * 4];
    float4 g4  = *(const float4*)&gk[lane * 4];
    float4 bt4 = *(const float4*)&btk[lane * 4];
    unsigned long long b01, b23;
    asm("mov.b64 %0,{%1,%2};" : "=l"(b01) : "f"(b4.x), "f"(b4.y));
    asm("mov.b64 %0,{%1,%2};" : "=l"(b23) : "f"(b4.z), "f"(b4.w));

    for (int n = n0 + gw; n < n1; n += NW) {
        int s0 = g_start[n], s1 = g_start[n + 1];
        if (s0 == s1) continue;

        ulonglong2 Mr[HDIM];
        const ulonglong2* Mp =
            (const ulonglong2*)(g_M + (size_t)(n - n0) * MCOLS + lane * 4);
#pragma unroll
        for (int k = 0; k < HDIM; k++) Mr[k] = Mp[k * 32];

        for (int jb = s0; jb < s1; jb += 32) {
            int cnt = s1 - jb; if (cnt > 32) cnt = 32;
            int d_l = 0;
            if (lane < cnt) d_l = dst[g_order[jb + lane]];

            int dcur = __shfl_sync(0xffffffffu, d_l, 0);
            const float4* hp = (const float4*)(g_h + (size_t)dcur * HDIM);
            float4 hc0 = hp[0], hc1 = hp[1], hc2 = hp[2], hc3 = hp[3], hc4 = hp[4];

            for (int t = 0; t < cnt; t++) {
                int tn = (t + 1 < cnt) ? t + 1 : t;
                int dnext = __shfl_sync(0xffffffffu, d_l, tn);
                const float4* hq = (const float4*)(g_h + (size_t)dnext * HDIM);
                float4 p0 = hq[0], p1 = hq[1], p2 = hq[2], p3 = hq[3], p4 = hq[4];

                float hd[HDIM] = {hc0.x, hc0.y, hc0.z, hc0.w,
                                  hc1.x, hc1.y, hc1.z, hc1.w,
                                  hc2.x, hc2.y, hc2.z, hc2.w,
                                  hc3.x, hc3.y, hc3.z, hc3.w,
                                  hc4.x, hc4.y, hc4.z, hc4.w};
                unsigned long long a01 = b01, a23 = b23;
#pragma unroll
                for (int k = 0; k < HDIM; k++) {
                    unsigned long long h2;
                    asm("mov.b64 %0,{%1,%1};" : "=l"(h2) : "f"(hd[k]));
                    asm("fma.rn.f32x2 %0, %1, %2, %0;" : "+l"(a01) : "l"(h2), "l"(Mr[k].x));
                    asm("fma.rn.f32x2 %0, %1, %2, %0;" : "+l"(a23) : "l"(h2), "l"(Mr[k].y));
                }
                float v0, v1, v2, v3;
                asm("mov.b64 {%0,%1},%2;" : "=f"(v0), "=f"(v1) : "l"(a01));
                asm("mov.b64 {%0,%1},%2;" : "=f"(v2), "=f"(v3) : "l"(a23));

                float s  = (v0 + v1) + (v2 + v3);
                float s2 = fmaf(v0, v0, fmaf(v1, v1, fmaf(v2, v2, v3 * v3)));
#pragma unroll
                for (int off = 16; off > 0; off >>= 1) {
                    s  += __shfl_xor_sync(0xffffffffu, s,  off);
                    s2 += __shfl_xor_sync(0xffffffffu, s2, off);
                }
                float m   = s * (1.0f / OUTD);
                float var = fmaf(-m, m, s2 * (1.0f / OUTD));
                float r   = rsqrtf(var + LN_EPS);

                float o0 = fmaf((v0 - m) * r, g4.x, bt4.x); o0 = o0 > 0.f ? o0 : 0.f;
                float o1 = fmaf((v1 - m) * r, g4.y, bt4.y); o1 = o1 > 0.f ? o1 : 0.f;
                float o2 = fmaf((v2 - m) * r, g4.z, bt4.z); o2 = o2 > 0.f ? o2 : 0.f;
                float o3 = fmaf((v3 - m) * r, g4.w, bt4.w); o3 = o3 > 0.f ? o3 : 0.f;

                red_add_v4(out + (size_t)dcur * OUTD + lane * 4, o0, o1, o2, o3);

                hc0 = p0; hc1 = p1; hc2 = p2; hc3 = p3; hc4 = p4;
                dcur = dnext;
            }
        }
    }
}

// ---------------------------------------------------------------------------
// Launch. Inputs resolved by element count (robust to ordering):
//   12.8M -> node_feat | 5120 -> W_node | 51200 -> W_kron
//   20-sized in order  -> b_node, g_node, beta_node
//   128-sized in order -> b_kron, g_kron, beta_kron
//   800000-sized in order -> src, dst   (int32: jnp downcasts int64 w/o x64)
// ---------------------------------------------------------------------------
extern "C" void kernel_launch(void* const* d_in, const int* in_sizes, int n_in,
                              void* d_out, int out_size)
{
    const float* node_feat = 0;
    const float* W_node = 0;
    const float* W_kron = 0;
    const float* p20[3]  = {0, 0, 0};
    const float* p128[3] = {0, 0, 0};
    const int*   pE[2]   = {0, 0};
    int n20 = 0, n128 = 0, nE = 0;
    int E = 0, N = 0;

    for (int i = 0; i < n_in; i++) {
        int sz = in_sizes[i];
        if (sz == GF * HDIM) {
            W_node = (const float*)d_in[i];
        } else if (sz == K400 * OUTD) {
            W_kron = (const float*)d_in[i];
        } else if (sz == HDIM) {
            if (n20 < 3) p20[n20++] = (const float*)d_in[i];
        } else if (sz == OUTD) {
            if (n128 < 3) p128[n128++] = (const float*)d_in[i];
        } else if (sz > 1000000) {
            node_feat = (const float*)d_in[i];
            N = sz / GF;
        } else {
            if (nE < 2) { pE[nE++] = (const int*)d_in[i]; E = sz; }
        }
    }
    const int* src = pE[0];
    const int* dst = pE[1];
    float* out = (float*)d_out;

    cudaMemsetAsync(out, 0, (size_t)out_size * sizeof(float));

    // A: node projections
    node_proj_kernel<<<(N + 7) / 8, 256>>>(node_feat, W_node, p20[0], p20[1],
                                           p20[2], N);
    // sort edges by src
    zero_cnt_kernel<<<(N + 255) / 256, 256>>>(N);
    hist_kernel<<<592, 256>>>(src, E);
    scan_kernel<<<1, 1024>>>(N);
    scatter_kernel<<<592, 256>>>(src, E);

    // Chunked: build M tile, then consume it while it's L2-resident
    for (int c0 = 0; c0 < N; c0 += CHUNK) {
        int c1 = c0 + CHUNK; if (c1 > N) c1 = N;
        m_build_kernel<<<(c1 - c0 + MB_NODES - 1) / MB_NODES, 256>>>(W_kron, c0, c1);
        edge_group_kernel<<<148 * 4, 128>>>(p128[0], p128[1], p128[2],
                                            dst, out, c0, c1);
    }
}

// round 7
// speedup vs baseline: 2.6146x; 1.2810x over previous
#include <cuda_runtime.h>
#include <cstdint>

// Shape: N=50000, GF=256, H=20, E=800000, K=400, OUT=128
#define GF      256
#define HDIM    20
#define HPAD    21              // padded smem stride (bank-conflict-free)
#define K400    400
#define OUTD    128
#define LN_EPS  1e-5f
#define MAX_N   50000
#define MAX_E   800000
#define MCOLS   (HDIM * OUTD)   // 2560
#define CHUNK   6400            // nodes per M tile (65.5 MB, fits L2)
#define SCAN_TILE 1024
#define MAX_SB  ((MAX_N + SCAN_TILE - 1) / SCAN_TILE)   // 49

// ---- device scratch (allocation-free rule) ----
__device__ float g_h[MAX_N * HDIM];                    // node projections
__device__ float g_M[(size_t)CHUNK * MCOLS];           // per-chunk M tile (65.5 MB)
__device__ int   g_cnt[MAX_N];
__device__ int   g_start[MAX_N + 1];
__device__ int   g_cursor[MAX_N];
__device__ int   g_order[MAX_E];
__device__ int   g_bsum[MAX_SB];

// ---------------------------------------------------------------------------
// Kernel A: h = relu(LayerNorm(node_feat @ W_node + b_node))   [N, 20]
// ---------------------------------------------------------------------------
__global__ __launch_bounds__(256) void node_proj_kernel(
    const float* __restrict__ x, const float* __restrict__ Wn,
    const float* __restrict__ bn, const float* __restrict__ gn,
    const float* __restrict__ btn, int N)
{
    __shared__ float Ws[GF * HPAD];
    __shared__ float bs[HDIM], gs[HDIM], bts[HDIM];

    int tid = threadIdx.x;
    for (int i = tid; i < GF * HDIM; i += blockDim.x)
        Ws[(i / HDIM) * HPAD + (i % HDIM)] = Wn[i];
    if (tid < HDIM) { bs[tid] = bn[tid]; gs[tid] = gn[tid]; bts[tid] = btn[tid]; }
    __syncthreads();

    int warp = tid >> 5, lane = tid & 31;
    int n = blockIdx.x * (blockDim.x >> 5) + warp;
    if (n >= N) return;

    float acc[HDIM];
#pragma unroll
    for (int o = 0; o < HDIM; o++) acc[o] = 0.f;

    const float* xr = x + (size_t)n * GF;
#pragma unroll 2
    for (int k = lane; k < GF; k += 32) {
        float xv = xr[k];
#pragma unroll
        for (int o = 0; o < HDIM; o++)
            acc[o] = fmaf(xv, Ws[k * HPAD + o], acc[o]);
    }
#pragma unroll
    for (int o = 0; o < HDIM; o++) {
#pragma unroll
        for (int s = 16; s > 0; s >>= 1)
            acc[o] += __shfl_xor_sync(0xffffffffu, acc[o], s);
    }
    if (lane == 0) {
        float s = 0.f, s2 = 0.f;
#pragma unroll
        for (int o = 0; o < HDIM; o++) {
            float v = acc[o] + bs[o];
            acc[o] = v; s += v; s2 = fmaf(v, v, s2);
        }
        float mu  = s * (1.0f / HDIM);
        float var = fmaf(-mu, mu, s2 * (1.0f / HDIM));
        float r   = rsqrtf(var + LN_EPS);
#pragma unroll
        for (int o = 0; o < HDIM; o++) {
            float v = fmaf((acc[o] - mu) * r, gs[o], bts[o]);
            g_h[(size_t)n * HDIM + o] = v > 0.f ? v : 0.f;
        }
    }
}

// ---------------------------------------------------------------------------
// Sort-by-src: zero -> histogram -> hierarchical scan (3 kernels) -> scatter
// ---------------------------------------------------------------------------
__global__ void zero_cnt_kernel(int N) {
    int i = blockIdx.x * blockDim.x + threadIdx.x;
    if (i < N) g_cnt[i] = 0;
}

__global__ void hist_kernel(const int* __restrict__ src, int E) {
    for (int e = blockIdx.x * blockDim.x + threadIdx.x; e < E;
         e += gridDim.x * blockDim.x)
        atomicAdd(&g_cnt[src[e]], 1);
}

// scan pass 1: per-1024-tile sums
__global__ __launch_bounds__(256) void scan_sum_kernel(int N) {
    __shared__ int ws[8];
    int b = blockIdx.x, t = threadIdx.x;
    int base = b * SCAN_TILE + t * 4;
    int s = 0;
#pragma unroll
    for (int j = 0; j < 4; j++) { int i = base + j; if (i < N) s += g_cnt[i]; }
#pragma unroll
    for (int o = 16; o > 0; o >>= 1) s += __shfl_xor_sync(0xffffffffu, s, o);
    if ((t & 31) == 0) ws[t >> 5] = s;
    __syncthreads();
    if (t < 32) {
        int v = (t < 8) ? ws[t] : 0;
#pragma unroll
        for (int o = 4; o > 0; o >>= 1) v += __shfl_xor_sync(0xffffffffu, v, o);
        if (t == 0) g_bsum[b] = v;
    }
}

// scan pass 2: exclusive scan of tile sums (NB <= 64), also writes total
__global__ __launch_bounds__(64) void scan_blocks_kernel(int NB, int N) {
    __shared__ int w0;
    int t = threadIdx.x, lane = t & 31, wid = t >> 5;
    int v = (t < NB) ? g_bsum[t] : 0;
    int x = v;
#pragma unroll
    for (int o = 1; o < 32; o <<= 1) {
        int y = __shfl_up_sync(0xffffffffu, x, o);
        if (lane >= o) x += y;
    }
    if (wid == 0 && lane == 31) w0 = x;
    __syncthreads();
    if (wid == 1) x += w0;
    if (t < NB) g_bsum[t] = x - v;          // exclusive prefix
    if (t == NB - 1) g_start[N] = x;        // grand total
}

// scan pass 3: write g_start / g_cursor
__global__ __launch_bounds__(256) void scan_write_kernel(int N) {
    __shared__ int wsum[8], woff[8];
    int b = blockIdx.x, t = threadIdx.x, lane = t & 31, wid = t >> 5;
    int base = b * SCAN_TILE + t * 4;

    int c[4]; int s = 0;
#pragma unroll
    for (int j = 0; j < 4; j++) {
        c[j] = (base + j < N) ? g_cnt[base + j] : 0;
        s += c[j];
    }
    int x = s;
#pragma unroll
    for (int o = 1; o < 32; o <<= 1) {
        int y = __shfl_up_sync(0xffffffffu, x, o);
        if (lane >= o) x += y;
    }
    if (lane == 31) wsum[wid] = x;
    __syncthreads();
    if (t < 32) {
        int v = (t < 8) ? wsum[t] : 0;
        int xi = v;
#pragma unroll
        for (int o = 1; o < 8; o <<= 1) {
            int y = __shfl_up_sync(0xffffffffu, xi, o);
            if (lane >= o) xi += y;
        }
        if (t < 8) woff[t] = xi - v;
    }
    __syncthreads();

    int run = g_bsum[b] + woff[wid] + (x - s);
#pragma unroll
    for (int j = 0; j < 4; j++) {
        int i = base + j;
        if (i < N) {
            g_start[i]  = run;
            g_cursor[i] = run;
            run += c[j];
        }
    }
}

__global__ void scatter_kernel(const int* __restrict__ src, int E) {
    for (int e = blockIdx.x * blockDim.x + threadIdx.x; e < E;
         e += gridDim.x * blockDim.x) {
        int p = atomicAdd(&g_cursor[src[e]], 1);
        g_order[p] = e;
    }
}

// ---------------------------------------------------------------------------
// Kernel B (chunked): for n in [n0,n1):
//   M[n-n0][k*128+o] = sum_a h[n][a] * W[a*20+k][o]
// 16 nodes/CTA -> 400 blocks/chunk (balanced across 148 SMs).
// ---------------------------------------------------------------------------
#define MB_NODES 16

__global__ __launch_bounds__(256) void m_build_kernel(
    const float* __restrict__ Wk, int n0, int n1)
{
    __shared__ float h_t[HDIM][MB_NODES];   // transposed h tile
    int tid = threadIdx.x;
    int nb = n0 + blockIdx.x * MB_NODES;

    for (int idx = tid; idx < MB_NODES * HDIM; idx += 256) {
        int i = idx / HDIM, a = idx % HDIM;
        float v = 0.f;
        if (nb + i < n1) v = g_h[(size_t)(nb + i) * HDIM + a];
        h_t[a][i] = v;
    }
    __syncthreads();

    for (int q = tid; q < MCOLS / 4; q += 256) {     // 640 quads
        int c = q * 4;
        int k = c >> 7;          // c / 128
        int o = c & 127;
        ulonglong2 Wq[HDIM];
#pragma unroll
        for (int a = 0; a < HDIM; a++)
            Wq[a] = *(const ulonglong2*)&Wk[(a * HDIM + k) * OUTD + o];

        for (int i4 = 0; i4 < MB_NODES; i4 += 4) {
            ulonglong2 acc[4];
#pragma unroll
            for (int ni = 0; ni < 4; ni++) { acc[ni].x = 0ull; acc[ni].y = 0ull; }
#pragma unroll
            for (int a = 0; a < HDIM; a++) {
                float4 h4 = *(const float4*)&h_t[a][i4];
                unsigned long long hx, hy, hz, hw;
                asm("mov.b64 %0,{%1,%1};" : "=l"(hx) : "f"(h4.x));
                asm("mov.b64 %0,{%1,%1};" : "=l"(hy) : "f"(h4.y));
                asm("mov.b64 %0,{%1,%1};" : "=l"(hz) : "f"(h4.z));
                asm("mov.b64 %0,{%1,%1};" : "=l"(hw) : "f"(h4.w));
                asm("fma.rn.f32x2 %0, %1, %2, %0;" : "+l"(acc[0].x) : "l"(hx), "l"(Wq[a].x));
                asm("fma.rn.f32x2 %0, %1, %2, %0;" : "+l"(acc[0].y) : "l"(hx), "l"(Wq[a].y));
                asm("fma.rn.f32x2 %0, %1, %2, %0;" : "+l"(acc[1].x) : "l"(hy), "l"(Wq[a].x));
                asm("fma.rn.f32x2 %0, %1, %2, %0;" : "+l"(acc[1].y) : "l"(hy), "l"(Wq[a].y));
                asm("fma.rn.f32x2 %0, %1, %2, %0;" : "+l"(acc[2].x) : "l"(hz), "l"(Wq[a].x));
                asm("fma.rn.f32x2 %0, %1, %2, %0;" : "+l"(acc[2].y) : "l"(hz), "l"(Wq[a].y));
                asm("fma.rn.f32x2 %0, %1, %2, %0;" : "+l"(acc[3].x) : "l"(hw), "l"(Wq[a].x));
                asm("fma.rn.f32x2 %0, %1, %2, %0;" : "+l"(acc[3].y) : "l"(hw), "l"(Wq[a].y));
            }
#pragma unroll
            for (int ni = 0; ni < 4; ni++) {
                int n = nb + i4 + ni;
                if (n < n1)
                    *(ulonglong2*)&g_M[(size_t)(n - n0) * MCOLS + c] = acc[ni];
            }
        }
    }
}

// ---------------------------------------------------------------------------
// Kernel D (chunked): grouped edges for src nodes in [n0,n1). Warp owns node
// n: caches M_n in regs (lane: cols lane*4..+3, all k), streams its edges:
//   y = h_dst @ M_n + b  -> LN -> ReLU -> red.global.add to out[dst]
// ---------------------------------------------------------------------------
__device__ __forceinline__ void red_add_v4(float* p, float a, float b, float c, float d) {
    asm volatile("red.global.add.v4.f32 [%0], {%1,%2,%3,%4};"
                 :: "l"(p), "f"(a), "f"(b), "f"(c), "f"(d) : "memory");
}

__global__ __launch_bounds__(128) void edge_group_kernel(
    const float* __restrict__ bk, const float* __restrict__ gk,
    const float* __restrict__ btk, const int* __restrict__ dst,
    float* __restrict__ out, int n0, int n1)
{
    int lane = threadIdx.x & 31;
    int gw   = (blockIdx.x * blockDim.x + threadIdx.x) >> 5;
    int NW   = (gridDim.x * blockDim.x) >> 5;

    float4 b4  = *(const float4*)&bk[lane * 4];
    float4 g4  = *(const float4*)&gk[lane * 4];
    float4 bt4 = *(const float4*)&btk[lane * 4];
    unsigned long long b01, b23;
    asm("mov.b64 %0,{%1,%2};" : "=l"(b01) : "f"(b4.x), "f"(b4.y));
    asm("mov.b64 %0,{%1,%2};" : "=l"(b23) : "f"(b4.z), "f"(b4.w));

    for (int n = n0 + gw; n < n1; n += NW) {
        int s0 = g_start[n], s1 = g_start[n + 1];
        if (s0 == s1) continue;

        ulonglong2 Mr[HDIM];
        const ulonglong2* Mp =
            (const ulonglong2*)(g_M + (size_t)(n - n0) * MCOLS + lane * 4);
#pragma unroll
        for (int k = 0; k < HDIM; k++) Mr[k] = Mp[k * 32];

        for (int jb = s0; jb < s1; jb += 32) {
            int cnt = s1 - jb; if (cnt > 32) cnt = 32;
            int d_l = 0;
            if (lane < cnt) d_l = dst[g_order[jb + lane]];

            int dcur = __shfl_sync(0xffffffffu, d_l, 0);
            const float4* hp = (const float4*)(g_h + (size_t)dcur * HDIM);
            float4 hc0 = hp[0], hc1 = hp[1], hc2 = hp[2], hc3 = hp[3], hc4 = hp[4];

            for (int t = 0; t < cnt; t++) {
                int tn = (t + 1 < cnt) ? t + 1 : t;
                int dnext = __shfl_sync(0xffffffffu, d_l, tn);
                const float4* hq = (const float4*)(g_h + (size_t)dnext * HDIM);
                float4 p0 = hq[0], p1 = hq[1], p2 = hq[2], p3 = hq[3], p4 = hq[4];

                float hd[HDIM] = {hc0.x, hc0.y, hc0.z, hc0.w,
                                  hc1.x, hc1.y, hc1.z, hc1.w,
                                  hc2.x, hc2.y, hc2.z, hc2.w,
                                  hc3.x, hc3.y, hc3.z, hc3.w,
                                  hc4.x, hc4.y, hc4.z, hc4.w};
                unsigned long long a01 = b01, a23 = b23;
#pragma unroll
                for (int k = 0; k < HDIM; k++) {
                    unsigned long long h2;
                    asm("mov.b64 %0,{%1,%1};" : "=l"(h2) : "f"(hd[k]));
                    asm("fma.rn.f32x2 %0, %1, %2, %0;" : "+l"(a01) : "l"(h2), "l"(Mr[k].x));
                    asm("fma.rn.f32x2 %0, %1, %2, %0;" : "+l"(a23) : "l"(h2), "l"(Mr[k].y));
                }
                float v0, v1, v2, v3;
                asm("mov.b64 {%0,%1},%2;" : "=f"(v0), "=f"(v1) : "l"(a01));
                asm("mov.b64 {%0,%1},%2;" : "=f"(v2), "=f"(v3) : "l"(a23));

                float s  = (v0 + v1) + (v2 + v3);
                float s2 = fmaf(v0, v0, fmaf(v1, v1, fmaf(v2, v2, v3 * v3)));
#pragma unroll
                for (int off = 16; off > 0; off >>= 1) {
                    s  += __shfl_xor_sync(0xffffffffu, s,  off);
                    s2 += __shfl_xor_sync(0xffffffffu, s2, off);
                }
                float m   = s * (1.0f / OUTD);
                float var = fmaf(-m, m, s2 * (1.0f / OUTD));
                float r   = rsqrtf(var + LN_EPS);

                float o0 = fmaf((v0 - m) * r, g4.x, bt4.x); o0 = o0 > 0.f ? o0 : 0.f;
                float o1 = fmaf((v1 - m) * r, g4.y, bt4.y); o1 = o1 > 0.f ? o1 : 0.f;
                float o2 = fmaf((v2 - m) * r, g4.z, bt4.z); o2 = o2 > 0.f ? o2 : 0.f;
                float o3 = fmaf((v3 - m) * r, g4.w, bt4.w); o3 = o3 > 0.f ? o3 : 0.f;

                red_add_v4(out + (size_t)dcur * OUTD + lane * 4, o0, o1, o2, o3);

                hc0 = p0; hc1 = p1; hc2 = p2; hc3 = p3; hc4 = p4;
                dcur = dnext;
            }
        }
    }
}

// ---------------------------------------------------------------------------
// Launch. Inputs resolved by element count (robust to ordering).
// Launch order places m_build chunk-1 at position #5 (memset counted) so the
// harness's ncu capture (-s 5 -c 1, empirically hits launch #5) profiles the
// suspected-heaviest kernel.
// ---------------------------------------------------------------------------
extern "C" void kernel_launch(void* const* d_in, const int* in_sizes, int n_in,
                              void* d_out, int out_size)
{
    const float* node_feat = 0;
    const float* W_node = 0;
    const float* W_kron = 0;
    const float* p20[3]  = {0, 0, 0};
    const float* p128[3] = {0, 0, 0};
    const int*   pE[2]   = {0, 0};
    int n20 = 0, n128 = 0, nE = 0;
    int E = 0, N = 0;

    for (int i = 0; i < n_in; i++) {
        int sz = in_sizes[i];
        if (sz == GF * HDIM) {
            W_node = (const float*)d_in[i];
        } else if (sz == K400 * OUTD) {
            W_kron = (const float*)d_in[i];
        } else if (sz == HDIM) {
            if (n20 < 3) p20[n20++] = (const float*)d_in[i];
        } else if (sz == OUTD) {
            if (n128 < 3) p128[n128++] = (const float*)d_in[i];
        } else if (sz > 1000000) {
            node_feat = (const float*)d_in[i];
            N = sz / GF;
        } else {
            if (nE < 2) { pE[nE++] = (const int*)d_in[i]; E = sz; }
        }
    }
    const int* src = pE[0];
    const int* dst = pE[1];
    float* out = (float*)d_out;

    int NB = (N + SCAN_TILE - 1) / SCAN_TILE;   // scan tiles (49)

    // #1 memset (counted by ncu), #2 node_proj, #3 zero, #4 hist,
    // #5 m_build chunk1  <-- ncu capture target
    cudaMemsetAsync(out, 0, (size_t)out_size * sizeof(float));
    node_proj_kernel<<<(N + 7) / 8, 256>>>(node_feat, W_node, p20[0], p20[1],
                                           p20[2], N);
    zero_cnt_kernel<<<(N + 255) / 256, 256>>>(N);
    hist_kernel<<<592, 256>>>(src, E);

    int c1_0 = 0, c1_1 = (CHUNK < N) ? CHUNK : N;
    m_build_kernel<<<(c1_1 - c1_0 + MB_NODES - 1) / MB_NODES, 256>>>(W_kron, c1_0, c1_1);

    // hierarchical scan + scatter
    scan_sum_kernel<<<NB, 256>>>(N);
    scan_blocks_kernel<<<1, 64>>>(NB, N);
    scan_write_kernel<<<NB, 256>>>(N);
    scatter_kernel<<<592, 256>>>(src, E);

    // consume chunk 1, then remaining chunks
    edge_group_kernel<<<148 * 4, 128>>>(p128[0], p128[1], p128[2], dst, out,
                                        c1_0, c1_1);
    for (int c0 = CHUNK; c0 < N; c0 += CHUNK) {
        int c1 = c0 + CHUNK; if (c1 > N) c1 = N;
        m_build_kernel<<<(c1 - c0 + MB_NODES - 1) / MB_NODES, 256>>>(W_kron, c0, c1);
        edge_group_kernel<<<148 * 4, 128>>>(p128[0], p128[1], p128[2],
                                            dst, out, c0, c1);
    }
}

// round 8
// speedup vs baseline: 2.8586x; 1.0933x over previous
#include <cuda_runtime.h>
#include <cstdint>

// Shape: N=50000, GF=256, H=20, E=800000, K=400, OUT=128
#define GF      256
#define HDIM    20
#define HPAD    21              // padded smem stride (bank-conflict-free)
#define K400    400
#define OUTD    128
#define LN_EPS  1e-5f
#define MAX_N   50000
#define MAX_E   800000
#define MCOLS   (HDIM * OUTD)   // 2560
#define CHUNK   6400            // nodes per M tile (65.5 MB, fits L2)
#define SCAN_TILE 1024
#define MAX_SB  ((MAX_N + SCAN_TILE - 1) / SCAN_TILE)   // 49

// ---- device scratch (allocation-free rule) ----
__device__ float g_h[MAX_N * HDIM];                    // node projections
__device__ float g_M[(size_t)CHUNK * MCOLS];           // per-chunk M tile (65.5 MB)
__device__ int   g_cnt[MAX_N];
__device__ int   g_start[MAX_N + 1];
__device__ int   g_cursor[MAX_N];
__device__ int   g_order[MAX_E];
__device__ int   g_dsts[MAX_E];                        // dst value in sorted order
__device__ int   g_bsum[MAX_SB];

// ---------------------------------------------------------------------------
// Kernel A: h = relu(LayerNorm(node_feat @ W_node + b_node))   [N, 20]
// ---------------------------------------------------------------------------
__global__ __launch_bounds__(256) void node_proj_kernel(
    const float* __restrict__ x, const float* __restrict__ Wn,
    const float* __restrict__ bn, const float* __restrict__ gn,
    const float* __restrict__ btn, int N)
{
    __shared__ float Ws[GF * HPAD];
    __shared__ float bs[HDIM], gs[HDIM], bts[HDIM];

    int tid = threadIdx.x;
    for (int i = tid; i < GF * HDIM; i += blockDim.x)
        Ws[(i / HDIM) * HPAD + (i % HDIM)] = Wn[i];
    if (tid < HDIM) { bs[tid] = bn[tid]; gs[tid] = gn[tid]; bts[tid] = btn[tid]; }
    __syncthreads();

    int warp = tid >> 5, lane = tid & 31;
    int n = blockIdx.x * (blockDim.x >> 5) + warp;
    if (n >= N) return;

    float acc[HDIM];
#pragma unroll
    for (int o = 0; o < HDIM; o++) acc[o] = 0.f;

    const float* xr = x + (size_t)n * GF;
#pragma unroll 2
    for (int k = lane; k < GF; k += 32) {
        float xv = xr[k];
#pragma unroll
        for (int o = 0; o < HDIM; o++)
            acc[o] = fmaf(xv, Ws[k * HPAD + o], acc[o]);
    }
#pragma unroll
    for (int o = 0; o < HDIM; o++) {
#pragma unroll
        for (int s = 16; s > 0; s >>= 1)
            acc[o] += __shfl_xor_sync(0xffffffffu, acc[o], s);
    }
    if (lane == 0) {
        float s = 0.f, s2 = 0.f;
#pragma unroll
        for (int o = 0; o < HDIM; o++) {
            float v = acc[o] + bs[o];
            acc[o] = v; s += v; s2 = fmaf(v, v, s2);
        }
        float mu  = s * (1.0f / HDIM);
        float var = fmaf(-mu, mu, s2 * (1.0f / HDIM));
        float r   = rsqrtf(var + LN_EPS);
#pragma unroll
        for (int o = 0; o < HDIM; o++) {
            float v = fmaf((acc[o] - mu) * r, gs[o], bts[o]);
            g_h[(size_t)n * HDIM + o] = v > 0.f ? v : 0.f;
        }
    }
}

// ---------------------------------------------------------------------------
// Sort-by-src: zero -> histogram -> hierarchical scan (3 kernels) -> scatter
// ---------------------------------------------------------------------------
__global__ void zero_cnt_kernel(int N) {
    int i = blockIdx.x * blockDim.x + threadIdx.x;
    if (i < N) g_cnt[i] = 0;
}

__global__ void hist_kernel(const int* __restrict__ src, int E) {
    for (int e = blockIdx.x * blockDim.x + threadIdx.x; e < E;
         e += gridDim.x * blockDim.x)
        atomicAdd(&g_cnt[src[e]], 1);
}

__global__ __launch_bounds__(256) void scan_sum_kernel(int N) {
    __shared__ int ws[8];
    int b = blockIdx.x, t = threadIdx.x;
    int base = b * SCAN_TILE + t * 4;
    int s = 0;
#pragma unroll
    for (int j = 0; j < 4; j++) { int i = base + j; if (i < N) s += g_cnt[i]; }
#pragma unroll
    for (int o = 16; o > 0; o >>= 1) s += __shfl_xor_sync(0xffffffffu, s, o);
    if ((t & 31) == 0) ws[t >> 5] = s;
    __syncthreads();
    if (t < 32) {
        int v = (t < 8) ? ws[t] : 0;
#pragma unroll
        for (int o = 4; o > 0; o >>= 1) v += __shfl_xor_sync(0xffffffffu, v, o);
        if (t == 0) g_bsum[b] = v;
    }
}

__global__ __launch_bounds__(64) void scan_blocks_kernel(int NB, int N) {
    __shared__ int w0;
    int t = threadIdx.x, lane = t & 31, wid = t >> 5;
    int v = (t < NB) ? g_bsum[t] : 0;
    int x = v;
#pragma unroll
    for (int o = 1; o < 32; o <<= 1) {
        int y = __shfl_up_sync(0xffffffffu, x, o);
        if (lane >= o) x += y;
    }
    if (wid == 0 && lane == 31) w0 = x;
    __syncthreads();
    if (wid == 1) x += w0;
    if (t < NB) g_bsum[t] = x - v;          // exclusive prefix
    if (t == NB - 1) g_start[N] = x;        // grand total
}

__global__ __launch_bounds__(256) void scan_write_kernel(int N) {
    __shared__ int wsum[8], woff[8];
    int b = blockIdx.x, t = threadIdx.x, lane = t & 31, wid = t >> 5;
    int base = b * SCAN_TILE + t * 4;

    int c[4]; int s = 0;
#pragma unroll
    for (int j = 0; j < 4; j++) {
        c[j] = (base + j < N) ? g_cnt[base + j] : 0;
        s += c[j];
    }
    int x = s;
#pragma unroll
    for (int o = 1; o < 32; o <<= 1) {
        int y = __shfl_up_sync(0xffffffffu, x, o);
        if (lane >= o) x += y;
    }
    if (lane == 31) wsum[wid] = x;
    __syncthreads();
    if (t < 32) {
        int v = (t < 8) ? wsum[t] : 0;
        int xi = v;
#pragma unroll
        for (int o = 1; o < 8; o <<= 1) {
            int y = __shfl_up_sync(0xffffffffu, xi, o);
            if (lane >= o) xi += y;
        }
        if (t < 8) woff[t] = xi - v;
    }
    __syncthreads();

    int run = g_bsum[b] + woff[wid] + (x - s);
#pragma unroll
    for (int j = 0; j < 4; j++) {
        int i = base + j;
        if (i < N) {
            g_start[i]  = run;
            g_cursor[i] = run;
            run += c[j];
        }
    }
}

__global__ void scatter_kernel(const int* __restrict__ src,
                               const int* __restrict__ dst, int E) {
    for (int e = blockIdx.x * blockDim.x + threadIdx.x; e < E;
         e += gridDim.x * blockDim.x) {
        int p = atomicAdd(&g_cursor[src[e]], 1);
        g_order[p] = e;
        g_dsts[p]  = dst[e];
    }
}

// ---------------------------------------------------------------------------
// Kernel B (chunked): M[n-n0][k*128+o] = sum_a h[n][a] * W[a*20+k][o]
// Persistent grid (296 = 2 CTAs/SM), tile-stride over 16-node tiles.
// ---------------------------------------------------------------------------
#define MB_NODES 16
#define MB_GRID  296

__global__ __launch_bounds__(256) void m_build_kernel(
    const float* __restrict__ Wk, int n0, int n1)
{
    __shared__ float h_t[HDIM][MB_NODES];   // transposed h tile
    int tid = threadIdx.x;
    int ntiles = (n1 - n0 + MB_NODES - 1) / MB_NODES;

    for (int tile = blockIdx.x; tile < ntiles; tile += gridDim.x) {
        int nb = n0 + tile * MB_NODES;
        __syncthreads();   // prior tile's h_t readers done
        for (int idx = tid; idx < MB_NODES * HDIM; idx += 256) {
            int i = idx / HDIM, a = idx % HDIM;
            float v = 0.f;
            if (nb + i < n1) v = g_h[(size_t)(nb + i) * HDIM + a];
            h_t[a][i] = v;
        }
        __syncthreads();

        for (int q = tid; q < MCOLS / 4; q += 256) {     // 640 quads
            int c = q * 4;
            int k = c >> 7;
            int o = c & 127;
            ulonglong2 Wq[HDIM];
#pragma unroll
            for (int a = 0; a < HDIM; a++)
                Wq[a] = *(const ulonglong2*)&Wk[(a * HDIM + k) * OUTD + o];

            for (int i4 = 0; i4 < MB_NODES; i4 += 4) {
                ulonglong2 acc[4];
#pragma unroll
                for (int ni = 0; ni < 4; ni++) { acc[ni].x = 0ull; acc[ni].y = 0ull; }
#pragma unroll
                for (int a = 0; a < HDIM; a++) {
                    float4 h4 = *(const float4*)&h_t[a][i4];
                    unsigned long long hx, hy, hz, hw;
                    asm("mov.b64 %0,{%1,%1};" : "=l"(hx) : "f"(h4.x));
                    asm("mov.b64 %0,{%1,%1};" : "=l"(hy) : "f"(h4.y));
                    asm("mov.b64 %0,{%1,%1};" : "=l"(hz) : "f"(h4.z));
                    asm("mov.b64 %0,{%1,%1};" : "=l"(hw) : "f"(h4.w));
                    asm("fma.rn.f32x2 %0, %1, %2, %0;" : "+l"(acc[0].x) : "l"(hx), "l"(Wq[a].x));
                    asm("fma.rn.f32x2 %0, %1, %2, %0;" : "+l"(acc[0].y) : "l"(hx), "l"(Wq[a].y));
                    asm("fma.rn.f32x2 %0, %1, %2, %0;" : "+l"(acc[1].x) : "l"(hy), "l"(Wq[a].x));
                    asm("fma.rn.f32x2 %0, %1, %2, %0;" : "+l"(acc[1].y) : "l"(hy), "l"(Wq[a].y));
                    asm("fma.rn.f32x2 %0, %1, %2, %0;" : "+l"(acc[2].x) : "l"(hz), "l"(Wq[a].x));
                    asm("fma.rn.f32x2 %0, %1, %2, %0;" : "+l"(acc[2].y) : "l"(hz), "l"(Wq[a].y));
                    asm("fma.rn.f32x2 %0, %1, %2, %0;" : "+l"(acc[3].x) : "l"(hw), "l"(Wq[a].x));
                    asm("fma.rn.f32x2 %0, %1, %2, %0;" : "+l"(acc[3].y) : "l"(hw), "l"(Wq[a].y));
                }
#pragma unroll
                for (int ni = 0; ni < 4; ni++) {
                    int n = nb + i4 + ni;
                    if (n < n1)
                        *(ulonglong2*)&g_M[(size_t)(n - n0) * MCOLS + c] = acc[ni];
                }
            }
        }
    }
}

// ---------------------------------------------------------------------------
// Kernel D (chunked) v2: grouped edges, 4-edge batched LN epilogue.
// Warp owns node n: caches M_n in regs (lane: cols lane*4..+3, all k),
// streams edges with h_dst prefetch; packed accumulators parked per slot;
// every 4 edges run the 8 shuffle-reduction chains interleaved.
// ---------------------------------------------------------------------------
__device__ __forceinline__ void red_add_v4(float* p, float a, float b, float c, float d) {
    asm volatile("red.global.add.v4.f32 [%0], {%1,%2,%3,%4};"
                 :: "l"(p), "f"(a), "f"(b), "f"(c), "f"(d) : "memory");
}

__device__ __forceinline__ void flush_ln(
    int nvalid,
    const unsigned long long* a01, const unsigned long long* a23,
    const int* dd, float4 g4, float4 bt4, float* out, int lane)
{
    float s[4], q[4];
#pragma unroll
    for (int i = 0; i < 4; i++) {
        float v0, v1, v2, v3;
        asm("mov.b64 {%0,%1},%2;" : "=f"(v0), "=f"(v1) : "l"(a01[i]));
        asm("mov.b64 {%0,%1},%2;" : "=f"(v2), "=f"(v3) : "l"(a23[i]));
        s[i] = (v0 + v1) + (v2 + v3);
        q[i] = fmaf(v0, v0, fmaf(v1, v1, fmaf(v2, v2, v3 * v3)));
    }
#pragma unroll
    for (int off = 16; off > 0; off >>= 1) {
#pragma unroll
        for (int i = 0; i < 4; i++) {
            s[i] += __shfl_xor_sync(0xffffffffu, s[i], off);
            q[i] += __shfl_xor_sync(0xffffffffu, q[i], off);
        }
    }
#pragma unroll
    for (int i = 0; i < 4; i++) {
        if (i >= nvalid) break;
        float m   = s[i] * (1.0f / OUTD);
        float var = fmaf(-m, m, q[i] * (1.0f / OUTD));
        float r   = rsqrtf(var + LN_EPS);
        float v0, v1, v2, v3;
        asm("mov.b64 {%0,%1},%2;" : "=f"(v0), "=f"(v1) : "l"(a01[i]));
        asm("mov.b64 {%0,%1},%2;" : "=f"(v2), "=f"(v3) : "l"(a23[i]));
        float o0 = fmaf((v0 - m) * r, g4.x, bt4.x); o0 = o0 > 0.f ? o0 : 0.f;
        float o1 = fmaf((v1 - m) * r, g4.y, bt4.y); o1 = o1 > 0.f ? o1 : 0.f;
        float o2 = fmaf((v2 - m) * r, g4.z, bt4.z); o2 = o2 > 0.f ? o2 : 0.f;
        float o3 = fmaf((v3 - m) * r, g4.w, bt4.w); o3 = o3 > 0.f ? o3 : 0.f;
        red_add_v4(out + (size_t)dd[i] * OUTD + lane * 4, o0, o1, o2, o3);
    }
}

__global__ __launch_bounds__(128, 3) void edge_group_kernel(
    const float* __restrict__ bk, const float* __restrict__ gk,
    const float* __restrict__ btk, float* __restrict__ out, int n0, int n1)
{
    int lane = threadIdx.x & 31;
    int gw   = (blockIdx.x * blockDim.x + threadIdx.x) >> 5;
    int NW   = (gridDim.x * blockDim.x) >> 5;

    float4 b4  = *(const float4*)&bk[lane * 4];
    float4 g4  = *(const float4*)&gk[lane * 4];
    float4 bt4 = *(const float4*)&btk[lane * 4];
    unsigned long long b01, b23;
    asm("mov.b64 %0,{%1,%2};" : "=l"(b01) : "f"(b4.x), "f"(b4.y));
    asm("mov.b64 %0,{%1,%2};" : "=l"(b23) : "f"(b4.z), "f"(b4.w));

    for (int n = n0 + gw; n < n1; n += NW) {
        int s0 = g_start[n], s1 = g_start[n + 1];
        if (s0 == s1) continue;

        ulonglong2 Mr[HDIM];
        const ulonglong2* Mp =
            (const ulonglong2*)(g_M + (size_t)(n - n0) * MCOLS + lane * 4);
#pragma unroll
        for (int k = 0; k < HDIM; k++) Mr[k] = Mp[k * 32];

        unsigned long long acc01[4], acc23[4];
        int dd[4];
        int slot = 0;

        for (int jb = s0; jb < s1; jb += 32) {
            int cnt = s1 - jb; if (cnt > 32) cnt = 32;
            int d_l = (lane < cnt) ? g_dsts[jb + lane] : 0;

            int dcur = __shfl_sync(0xffffffffu, d_l, 0);
            const float4* hp = (const float4*)(g_h + (size_t)dcur * HDIM);
            float4 hc0 = hp[0], hc1 = hp[1], hc2 = hp[2], hc3 = hp[3], hc4 = hp[4];

            for (int t = 0; t < cnt; t++) {
                int tn = (t + 1 < cnt) ? t + 1 : t;
                int dnext = __shfl_sync(0xffffffffu, d_l, tn);
                const float4* hq = (const float4*)(g_h + (size_t)dnext * HDIM);
                float4 p0 = hq[0], p1 = hq[1], p2 = hq[2], p3 = hq[3], p4 = hq[4];

                float hd[HDIM] = {hc0.x, hc0.y, hc0.z, hc0.w,
                                  hc1.x, hc1.y, hc1.z, hc1.w,
                                  hc2.x, hc2.y, hc2.z, hc2.w,
                                  hc3.x, hc3.y, hc3.z, hc3.w,
                                  hc4.x, hc4.y, hc4.z, hc4.w};
                unsigned long long a01 = b01, a23 = b23;
#pragma unroll
                for (int k = 0; k < HDIM; k++) {
                    unsigned long long h2;
                    asm("mov.b64 %0,{%1,%1};" : "=l"(h2) : "f"(hd[k]));
                    asm("fma.rn.f32x2 %0, %1, %2, %0;" : "+l"(a01) : "l"(h2), "l"(Mr[k].x));
                    asm("fma.rn.f32x2 %0, %1, %2, %0;" : "+l"(a23) : "l"(h2), "l"(Mr[k].y));
                }
                acc01[slot] = a01; acc23[slot] = a23; dd[slot] = dcur;
                slot++;
                if (slot == 4) {
                    flush_ln(4, acc01, acc23, dd, g4, bt4, out, lane);
                    slot = 0;
                }
                hc0 = p0; hc1 = p1; hc2 = p2; hc3 = p3; hc4 = p4;
                dcur = dnext;
            }
        }
        if (slot > 0)
            flush_ln(slot, acc01, acc23, dd, g4, bt4, out, lane);
    }
}

// ---------------------------------------------------------------------------
// Launch. Inputs resolved by element count. Launch order keeps m_build
// chunk-1 at position #5 (1-based, memset counted) = the ncu capture slot.
// ---------------------------------------------------------------------------
extern "C" void kernel_launch(void* const* d_in, const int* in_sizes, int n_in,
                              void* d_out, int out_size)
{
    const float* node_feat = 0;
    const float* W_node = 0;
    const float* W_kron = 0;
    const float* p20[3]  = {0, 0, 0};
    const float* p128[3] = {0, 0, 0};
    const int*   pE[2]   = {0, 0};
    int n20 = 0, n128 = 0, nE = 0;
    int E = 0, N = 0;

    for (int i = 0; i < n_in; i++) {
        int sz = in_sizes[i];
        if (sz == GF * HDIM) {
            W_node = (const float*)d_in[i];
        } else if (sz == K400 * OUTD) {
            W_kron = (const float*)d_in[i];
        } else if (sz == HDIM) {
            if (n20 < 3) p20[n20++] = (const float*)d_in[i];
        } else if (sz == OUTD) {
            if (n128 < 3) p128[n128++] = (const float*)d_in[i];
        } else if (sz > 1000000) {
            node_feat = (const float*)d_in[i];
            N = sz / GF;
        } else {
            if (nE < 2) { pE[nE++] = (const int*)d_in[i]; E = sz; }
        }
    }
    const int* src = pE[0];
    const int* dst = pE[1];
    float* out = (float*)d_out;

    int NB = (N + SCAN_TILE - 1) / SCAN_TILE;

    // #1 memset, #2 node_proj, #3 zero, #4 hist, #5 m_build chunk1 (ncu slot)
    cudaMemsetAsync(out, 0, (size_t)out_size * sizeof(float));
    node_proj_kernel<<<(N + 7) / 8, 256>>>(node_feat, W_node, p20[0], p20[1],
                                           p20[2], N);
    zero_cnt_kernel<<<(N + 255) / 256, 256>>>(N);
    hist_kernel<<<592, 256>>>(src, E);

    int c1_0 = 0, c1_1 = (CHUNK < N) ? CHUNK : N;
    m_build_kernel<<<MB_GRID, 256>>>(W_kron, c1_0, c1_1);

    scan_sum_kernel<<<NB, 256>>>(N);
    scan_blocks_kernel<<<1, 64>>>(NB, N);
    scan_write_kernel<<<NB, 256>>>(N);
    scatter_kernel<<<592, 256>>>(src, dst, E);

    edge_group_kernel<<<148 * 3, 128>>>(p128[0], p128[1], p128[2], out,
                                        c1_0, c1_1);
    for (int c0 = CHUNK; c0 < N; c0 += CHUNK) {
        int c1 = c0 + CHUNK; if (c1 > N) c1 = N;
        m_build_kernel<<<MB_GRID, 256>>>(W_kron, c0, c1);
        edge_group_kernel<<<148 * 3, 128>>>(p128[0], p128[1], p128[2], out,
                                            c0, c1);
    }
}